// round 8
// baseline (speedup 1.0000x reference)
#include <cuda_runtime.h>

#define NN 50000
#define EE 800000
#define BB 64

// ---------------- all arguments in one by-value struct ----------------
struct KParams {
    int phase;
    const float* x; const int* ei; const int* batch;
    const float *W1, *a1s, *a1d, *b1;
    const float *W2, *a2s, *a2d, *b2;
    const float *W3, *a3s, *a3d, *b3;
    const float *W4, *a4s, *a4d, *b4;
    const float *Wc1, *bc1, *Wc2, *bc2;
    float *recon, *latent, *pred;
};

// ---------------- device scratch (~3.2 MB) ----------------
__device__ unsigned short g_csr[EE];     // send ids grouped by recv (N<65536) 1.6MB
__device__ int   g_off[NN + 1];          // CSR offsets                        0.2MB
__device__ int   g_deg[NN];              // histogram / scatter cursor         0.2MB
__device__ float g_hsA[NN], g_hdA[NN];   // attention scalars A                0.4MB
__device__ float g_hsB[NN], g_hdB[NN];   // attention scalars B                0.4MB
__device__ float g_ch4[NN * 3];          // c = agg1(x); later h4              0.6MB
__device__ int   g_bsum[256];            // scan block sums
__device__ float g_pool[BB * 64];
__device__ int   g_cnt[BB];
__device__ int   g_flags[2];             // [0] ei int64?  [1] batch int64?
__device__ float g_w1s[3], g_w1d[3];
__device__ float g_w2s[128], g_w2d[128];
__device__ float g_w3s[64], g_w3d[64];

// ---------------- the single kernel, phase-dispatched ----------------
// Phases (grid x block):
//  0 init+detect (196x256)   1 proj (1x256)       2 hist (3125x256)
//  3 scan1 (196x256)         4 scan2 (1x256)      5 scan3 (196x256)
//  6 scatter (3125x256)      7 dots1 (196x256)    8 aggL1->c (6250x256)
//  9 dots2 (6250x256)       10 aggL2->latent     11 aggL3->h4
// 12 aggL4->recon           13 pool              14 cls (8x256)
__global__ void __launch_bounds__(256) gat_kernel(KParams p) {
    __shared__ float sf[1088];
    int* si = (int*)sf;
    const int t = threadIdx.x;
    const int b = blockIdx.x;
    const int ph = p.phase;

    if (ph == 0) {                       // ---- init + dtype detect ----
        int i = b * 256 + t;
        if (i < NN) g_deg[i] = 0;
        if (i < BB * 64) g_pool[i] = 0.f;
        if (i < BB) g_cnt[i] = 0;
        if (b == 0 && t < 64) {
            int lane = t & 31;
            int nz = 0;
            if (t < 32) {
                for (int k = lane; k < 128; k += 32) nz |= p.ei[2 * k + 1];
            } else {
                for (int k = lane; k < 128; k += 32) nz |= p.batch[NN - 256 + 2 * k + 1];
            }
            #pragma unroll
            for (int o = 16; o; o >>= 1) nz |= __shfl_xor_sync(0xffffffffu, nz, o);
            if (lane == 0) g_flags[t < 32 ? 0 : 1] = (nz == 0) ? 1 : 0;
        }
    } else if (ph == 1) {                // ---- projections of attention vectors ----
        if (t < 128) {
            float s = 0.f, d = 0.f;
            for (int k = 0; k < 64; k++) {
                float w = p.W2[t * 64 + k];
                s = fmaf(w, p.a2s[k], s);
                d = fmaf(w, p.a2d[k], d);
            }
            g_w2s[t] = s; g_w2d[t] = d;
        } else if (t < 192) {
            int i = t - 128;
            float s = 0.f, d = 0.f;
            for (int k = 0; k < 128; k++) {
                float w = p.W3[i * 128 + k];
                s = fmaf(w, p.a3s[k], s);
                d = fmaf(w, p.a3d[k], d);
            }
            g_w3s[i] = s; g_w3d[i] = d;
        } else if (t < 195) {
            int i = t - 192;
            float s = 0.f;
            for (int k = 0; k < 128; k++) s = fmaf(p.W1[i * 128 + k], p.a1s[k], s);
            g_w1s[i] = s;
        } else if (t < 198) {
            int i = t - 195;
            float d = 0.f;
            for (int k = 0; k < 128; k++) d = fmaf(p.W1[i * 128 + k], p.a1d[k], d);
            g_w1d[i] = d;
        }
    } else if (ph == 2) {                // ---- degree histogram ----
        int e = b * 256 + t;
        if (e < EE) {
            int r = g_flags[0] ? (int)((const long long*)p.ei)[(size_t)EE + e]
                               : p.ei[EE + e];
            atomicAdd(&g_deg[r], 1);
        }
    } else if (ph == 3) {                // ---- scan part 1: per-block ----
        int i = b * 256 + t;
        int v = (i < NN) ? g_deg[i] : 0;
        si[t] = v;
        __syncthreads();
        #pragma unroll
        for (int d = 1; d < 256; d <<= 1) {
            int tv = (t >= d) ? si[t - d] : 0;
            __syncthreads();
            si[t] += tv;
            __syncthreads();
        }
        if (i < NN) g_off[i] = si[t] - v;           // exclusive within block
        if (t == 255) g_bsum[b] = si[255];
    } else if (ph == 4) {                // ---- scan part 2: block sums ----
        int v = (t < 196) ? g_bsum[t] : 0;
        si[t] = v;
        __syncthreads();
        #pragma unroll
        for (int d = 1; d < 256; d <<= 1) {
            int tv = (t >= d) ? si[t - d] : 0;
            __syncthreads();
            si[t] += tv;
            __syncthreads();
        }
        if (t < 196) g_bsum[t] = si[t] - v;         // exclusive block offset
    } else if (ph == 5) {                // ---- scan part 3: add offsets ----
        int i = b * 256 + t;
        if (i < NN) {
            g_off[i] += g_bsum[b];
            g_deg[i] = 0;                            // reuse as scatter cursor
        }
        if (i == 0) g_off[NN] = EE;
    } else if (ph == 6) {                // ---- scatter to CSR ----
        int e = b * 256 + t;
        if (e < EE) {
            int r, s;
            if (g_flags[0]) {
                r = (int)((const long long*)p.ei)[(size_t)EE + e];
                s = (int)((const long long*)p.ei)[e];
            } else {
                r = p.ei[EE + e];
                s = p.ei[e];
            }
            int pos = g_off[r] + atomicAdd(&g_deg[r], 1);
            g_csr[pos] = (unsigned short)s;
        }
    } else if (ph == 7) {                // ---- layer-1 attention scalars ----
        int n = b * 256 + t;
        if (n < NN) {
            float x0 = p.x[n * 3 + 0], x1 = p.x[n * 3 + 1], x2 = p.x[n * 3 + 2];
            g_hsA[n] = x0 * g_w1s[0] + x1 * g_w1s[1] + x2 * g_w1s[2];
            g_hdA[n] = x0 * g_w1d[0] + x1 * g_w1d[1] + x2 * g_w1d[2];
        }
    } else if (ph == 8 || ph == 12) {    // ---- 3-dim aggregations (L1 / L4) ----
        int gw = (b * 256 + t) >> 5;
        int lane = t & 31;
        if (gw < NN) {
            const float* in = (ph == 8) ? p.x : g_ch4;
            const float* hs = (ph == 8) ? g_hsA : g_hsB;
            float hdi = (ph == 8) ? g_hdA[gw] : g_hdB[gw];
            int beg = g_off[gw], end = g_off[gw + 1];
            float s = 0.f, a0 = 0.f, a1 = 0.f, a2 = 0.f;
            for (int j = beg + lane; j < end; j += 32) {
                int sn = g_csr[j];
                float e = hs[sn] + hdi;
                e = e > 0.f ? e : 0.2f * e;
                float w = __expf(e);
                s += w;
                a0 = fmaf(w, in[sn * 3 + 0], a0);
                a1 = fmaf(w, in[sn * 3 + 1], a1);
                a2 = fmaf(w, in[sn * 3 + 2], a2);
            }
            #pragma unroll
            for (int o = 16; o; o >>= 1) {
                s  += __shfl_xor_sync(0xffffffffu, s, o);
                a0 += __shfl_xor_sync(0xffffffffu, a0, o);
                a1 += __shfl_xor_sync(0xffffffffu, a1, o);
                a2 += __shfl_xor_sync(0xffffffffu, a2, o);
            }
            float es = hs[gw] + hdi;
            es = es > 0.f ? es : 0.2f * es;
            float ws = __expf(es);
            s += ws;
            a0 = fmaf(ws, in[gw * 3 + 0], a0);
            a1 = fmaf(ws, in[gw * 3 + 1], a1);
            a2 = fmaf(ws, in[gw * 3 + 2], a2);
            float inv = 1.f / s;
            if (lane == 0) {
                if (ph == 8) {
                    g_ch4[gw * 3 + 0] = a0 * inv;
                    g_ch4[gw * 3 + 1] = a1 * inv;
                    g_ch4[gw * 3 + 2] = a2 * inv;
                } else {
                    p.recon[gw * 3 + 0] = a0 * inv + p.b4[0];
                    p.recon[gw * 3 + 1] = a1 * inv + p.b4[1];
                    p.recon[gw * 3 + 2] = a2 * inv + p.b4[2];
                }
            }
        }
    } else if (ph == 9) {                // ---- L2 attention scalars ----
        int gw = (b * 256 + t) >> 5;
        int lane = t & 31;
        if (gw < NN) {
            float c0 = g_ch4[gw * 3 + 0], c1 = g_ch4[gw * 3 + 1], c2 = g_ch4[gw * 3 + 2];
            int k0 = lane * 4;
            float4 w0 = *(const float4*)&p.W1[0 * 128 + k0];
            float4 w1 = *(const float4*)&p.W1[1 * 128 + k0];
            float4 w2 = *(const float4*)&p.W1[2 * 128 + k0];
            float4 bb = *(const float4*)&p.b1[k0];
            float z0 = fmaxf(fmaf(c0, w0.x, fmaf(c1, w1.x, fmaf(c2, w2.x, bb.x))), 0.f);
            float z1 = fmaxf(fmaf(c0, w0.y, fmaf(c1, w1.y, fmaf(c2, w2.y, bb.y))), 0.f);
            float z2 = fmaxf(fmaf(c0, w0.z, fmaf(c1, w1.z, fmaf(c2, w2.z, bb.z))), 0.f);
            float z3 = fmaxf(fmaf(c0, w0.w, fmaf(c1, w1.w, fmaf(c2, w2.w, bb.w))), 0.f);
            float4 vs = *(const float4*)&g_w2s[k0];
            float4 vd = *(const float4*)&g_w2d[k0];
            float s = z0 * vs.x + z1 * vs.y + z2 * vs.z + z3 * vs.w;
            float d = z0 * vd.x + z1 * vd.y + z2 * vd.z + z3 * vd.w;
            #pragma unroll
            for (int o = 16; o; o >>= 1) {
                s += __shfl_xor_sync(0xffffffffu, s, o);
                d += __shfl_xor_sync(0xffffffffu, d, o);
            }
            if (lane == 0) { g_hsB[gw] = s; g_hdB[gw] = d; }
        }
    } else if (ph == 10) {               // ---- fused L2: latent ----
        int gw = (b * 256 + t) >> 5;
        int wid = (t >> 5) & 7;
        int lane = t & 31;
        if (gw < NN) {
            float* zsh = &sf[wid * 128];
            int beg = g_off[gw], end = g_off[gw + 1];
            float hdi = g_hdB[gw];
            int k0 = lane * 4;
            float4 w0 = *(const float4*)&p.W1[0 * 128 + k0];
            float4 w1 = *(const float4*)&p.W1[1 * 128 + k0];
            float4 w2 = *(const float4*)&p.W1[2 * 128 + k0];
            float4 bb = *(const float4*)&p.b1[k0];
            float s = 0.f;
            float acx = 0.f, acy = 0.f, acz = 0.f, acw = 0.f;
            for (int j = beg; j <= end; j++) {
                int sn = (j < end) ? (int)g_csr[j] : gw;        // last iter = self loop
                float e = g_hsB[sn] + hdi;
                e = e > 0.f ? e : 0.2f * e;
                float w = __expf(e);
                s += w;
                float c0 = g_ch4[sn * 3 + 0], c1 = g_ch4[sn * 3 + 1], c2 = g_ch4[sn * 3 + 2];
                float z0 = fmaxf(fmaf(c0, w0.x, fmaf(c1, w1.x, fmaf(c2, w2.x, bb.x))), 0.f);
                float z1 = fmaxf(fmaf(c0, w0.y, fmaf(c1, w1.y, fmaf(c2, w2.y, bb.y))), 0.f);
                float z2 = fmaxf(fmaf(c0, w0.z, fmaf(c1, w1.z, fmaf(c2, w2.z, bb.z))), 0.f);
                float z3 = fmaxf(fmaf(c0, w0.w, fmaf(c1, w1.w, fmaf(c2, w2.w, bb.w))), 0.f);
                acx = fmaf(w, z0, acx);
                acy = fmaf(w, z1, acy);
                acz = fmaf(w, z2, acz);
                acw = fmaf(w, z3, acw);
            }
            float inv = 1.f / s;                                 // s uniform across lanes
            zsh[k0 + 0] = acx * inv;
            zsh[k0 + 1] = acy * inv;
            zsh[k0 + 2] = acz * inv;
            zsh[k0 + 3] = acw * inv;
            __syncwarp();
            int m = lane * 2;
            float o0 = p.b2[m], o1 = p.b2[m + 1];
            #pragma unroll 8
            for (int k = 0; k < 128; k++) {
                float zk = zsh[k];
                float2 w = *(const float2*)&p.W2[k * 64 + m];
                o0 = fmaf(zk, w.x, o0);
                o1 = fmaf(zk, w.y, o1);
            }
            p.latent[(size_t)gw * 64 + m]     = o0;
            p.latent[(size_t)gw * 64 + m + 1] = o1;
            float ss = o0 * g_w3s[m] + o1 * g_w3s[m + 1];
            float dd = o0 * g_w3d[m] + o1 * g_w3d[m + 1];
            #pragma unroll
            for (int o = 16; o; o >>= 1) {
                ss += __shfl_xor_sync(0xffffffffu, ss, o);
                dd += __shfl_xor_sync(0xffffffffu, dd, o);
            }
            if (lane == 0) { g_hsA[gw] = ss; g_hdA[gw] = dd; }
        }
    } else if (ph == 11) {               // ---- fused L3: h4 ----
        int gw = (b * 256 + t) >> 5;
        int wid = (t >> 5) & 7;
        int lane = t & 31;
        if (gw < NN) {
            float* dsh = &sf[wid * 64];
            int beg = g_off[gw], end = g_off[gw + 1];
            float hdi = g_hdA[gw];
            int m = lane * 2;
            float s = 0.f, ax = 0.f, ay = 0.f;
            for (int j = beg; j <= end; j++) {
                int sn = (j < end) ? (int)g_csr[j] : gw;        // last iter = self loop
                float e = g_hsA[sn] + hdi;
                e = e > 0.f ? e : 0.2f * e;
                float w = __expf(e);
                float vx = p.latent[(size_t)sn * 64 + m];
                float vy = p.latent[(size_t)sn * 64 + m + 1];
                s += w;
                ax = fmaf(w, vx, ax);
                ay = fmaf(w, vy, ay);
            }
            float inv = 1.f / s;
            dsh[m] = ax * inv;
            dsh[m + 1] = ay * inv;
            __syncwarp();
            int k0 = lane * 4;
            float4 acc = *(const float4*)&p.b3[k0];
            for (int i = 0; i < 64; i++) {
                float di = dsh[i];
                float4 w = *(const float4*)&p.W3[i * 128 + k0];
                acc.x = fmaf(di, w.x, acc.x);
                acc.y = fmaf(di, w.y, acc.y);
                acc.z = fmaf(di, w.z, acc.z);
                acc.w = fmaf(di, w.w, acc.w);
            }
            acc.x = fmaxf(acc.x, 0.f); acc.y = fmaxf(acc.y, 0.f);
            acc.z = fmaxf(acc.z, 0.f); acc.w = fmaxf(acc.w, 0.f);
            float a0 = acc.x * p.W4[(k0 + 0) * 3 + 0] + acc.y * p.W4[(k0 + 1) * 3 + 0]
                     + acc.z * p.W4[(k0 + 2) * 3 + 0] + acc.w * p.W4[(k0 + 3) * 3 + 0];
            float a1 = acc.x * p.W4[(k0 + 0) * 3 + 1] + acc.y * p.W4[(k0 + 1) * 3 + 1]
                     + acc.z * p.W4[(k0 + 2) * 3 + 1] + acc.w * p.W4[(k0 + 3) * 3 + 1];
            float a2 = acc.x * p.W4[(k0 + 0) * 3 + 2] + acc.y * p.W4[(k0 + 1) * 3 + 2]
                     + acc.z * p.W4[(k0 + 2) * 3 + 2] + acc.w * p.W4[(k0 + 3) * 3 + 2];
            #pragma unroll
            for (int o = 16; o; o >>= 1) {
                a0 += __shfl_xor_sync(0xffffffffu, a0, o);
                a1 += __shfl_xor_sync(0xffffffffu, a1, o);
                a2 += __shfl_xor_sync(0xffffffffu, a2, o);
            }
            if (lane == 0) {
                g_ch4[gw * 3 + 0] = a0;
                g_ch4[gw * 3 + 1] = a1;
                g_ch4[gw * 3 + 2] = a2;
                g_hsB[gw] = a0 * p.a4s[0] + a1 * p.a4s[1] + a2 * p.a4s[2];
                g_hdB[gw] = a0 * p.a4d[0] + a1 * p.a4d[1] + a2 * p.a4d[2];
            }
        }
    } else if (ph == 13) {               // ---- pooling ----
        int gw = (b * 256 + t) >> 5;
        int lane = t & 31;
        if (gw < NN) {
            int bi = g_flags[1] ? (int)((const long long*)p.batch)[gw] : p.batch[gw];
            atomicAdd(&g_pool[bi * 64 + lane], p.latent[(size_t)gw * 64 + lane]);
            atomicAdd(&g_pool[bi * 64 + lane + 32], p.latent[(size_t)gw * 64 + lane + 32]);
            if (lane == 0) atomicAdd(&g_cnt[bi], 1);
        }
    } else if (ph == 14) {               // ---- classifier (warp per graph) ----
        int wid = t >> 5;
        int lane = t & 31;
        int g = b * 8 + wid;
        if (g < BB) {
            float* pp = &sf[wid * 64];
            float invc = 1.f / fmaxf((float)g_cnt[g], 1.f);
            pp[lane] = g_pool[g * 64 + lane] * invc;
            pp[lane + 32] = g_pool[g * 64 + lane + 32] * invc;
            __syncwarp();
            float z = p.bc1[lane];
            #pragma unroll 8
            for (int d = 0; d < 64; d++) z = fmaf(pp[d], p.Wc1[d * 32 + lane], z);
            z = fmaxf(z, 0.f);
            float o0 = z * p.Wc2[lane * 2 + 0];
            float o1 = z * p.Wc2[lane * 2 + 1];
            #pragma unroll
            for (int o = 16; o; o >>= 1) {
                o0 += __shfl_xor_sync(0xffffffffu, o0, o);
                o1 += __shfl_xor_sync(0xffffffffu, o1, o);
            }
            if (lane == 0) {
                p.pred[g * 2 + 0] = o0 + p.bc2[0];
                p.pred[g * 2 + 1] = o1 + p.bc2[1];
            }
        }
    }
}

// ---------------- launcher ----------------
extern "C" void kernel_launch(void* const* d_in, const int* in_sizes, int n_in,
                              void* d_out, int out_size) {
    KParams p;
    p.x     = (const float*)d_in[0];
    p.ei    = (const int*)d_in[1];
    p.batch = (const int*)d_in[2];
    p.W1 = (const float*)d_in[3];  p.a1s = (const float*)d_in[4];
    p.a1d = (const float*)d_in[5]; p.b1  = (const float*)d_in[6];
    p.W2 = (const float*)d_in[7];  p.a2s = (const float*)d_in[8];
    p.a2d = (const float*)d_in[9]; p.b2  = (const float*)d_in[10];
    p.W3 = (const float*)d_in[11]; p.a3s = (const float*)d_in[12];
    p.a3d = (const float*)d_in[13];p.b3  = (const float*)d_in[14];
    p.W4 = (const float*)d_in[15]; p.a4s = (const float*)d_in[16];
    p.a4d = (const float*)d_in[17];p.b4  = (const float*)d_in[18];
    p.Wc1 = (const float*)d_in[19];p.bc1 = (const float*)d_in[20];
    p.Wc2 = (const float*)d_in[21];p.bc2 = (const float*)d_in[22];
    p.recon  = (float*)d_out;
    p.latent = (float*)d_out + 150000;
    p.pred   = (float*)d_out + 150000 + 3200000;

    const int nGrid = (NN + 255) / 256;          // 196
    const int eGrid = (EE + 255) / 256;          // 3125
    const int wGrid = (NN * 32 + 255) / 256;     // 6250

    p.phase = 0;  gat_kernel<<<nGrid, 256>>>(p);   // init + detect
    p.phase = 1;  gat_kernel<<<1, 256>>>(p);       // projections
    p.phase = 2;  gat_kernel<<<eGrid, 256>>>(p);   // histogram
    p.phase = 3;  gat_kernel<<<nGrid, 256>>>(p);   // scan (block)
    p.phase = 4;  gat_kernel<<<1, 256>>>(p);       // scan (sums)
    p.phase = 5;  gat_kernel<<<nGrid, 256>>>(p);   // scan (add)
    p.phase = 6;  gat_kernel<<<eGrid, 256>>>(p);   // scatter -> CSR
    p.phase = 7;  gat_kernel<<<nGrid, 256>>>(p);   // dots1
    p.phase = 8;  gat_kernel<<<wGrid, 256>>>(p);   // L1 agg -> c
    p.phase = 9;  gat_kernel<<<wGrid, 256>>>(p);   // dots2
    p.phase = 10; gat_kernel<<<wGrid, 256>>>(p);   // L2 fused -> latent
    p.phase = 11; gat_kernel<<<wGrid, 256>>>(p);   // L3 fused -> h4
    p.phase = 12; gat_kernel<<<wGrid, 256>>>(p);   // L4 agg -> recon
    p.phase = 13; gat_kernel<<<wGrid, 256>>>(p);   // pooling
    p.phase = 14; gat_kernel<<<8, 256>>>(p);       // classifier
}

// round 9
// speedup vs baseline: 1.0617x; 1.0617x over previous
#include <cuda_runtime.h>

#define NN 50000
#define EE 800000
#define BB 64

// ---------------- all arguments in one by-value struct ----------------
struct KParams {
    int phase;
    const float* x; const int* ei; const int* batch;
    const float *W1, *a1s, *a1d, *b1;
    const float *W2, *a2s, *a2d, *b2;
    const float *W3, *a3s, *a3d, *b3;
    const float *W4, *a4s, *a4d, *b4;
    const float *Wc1, *bc1, *Wc2, *bc2;
    float *recon, *latent, *pred;
};

// ---------------- device scratch (~4.6 MB) ----------------
__device__ unsigned short g_csr[EE];     // send ids grouped by recv (N<65536)
__device__ int    g_off[NN + 1];         // CSR offsets
__device__ int    g_deg[NN];             // histogram / scatter cursor
__device__ float4 g_pkA[NN];             // (x0,x1,x2,hs1); later (h4_0..2,hs4)
__device__ float4 g_pkB[NN];             // (c0,c1,c2,hs2)
__device__ float  g_hsA[NN];             // latent-based src scalars (L3)
__device__ float  g_hdA[NN];             // dst scalars (L1, then L3)
__device__ float  g_hdB[NN];             // dst scalars (L2, then L4)
__device__ int    g_bsum[256];
__device__ float  g_pool[BB * 64];
__device__ int    g_cnt[BB];
__device__ int    g_flags[2];            // [0] ei int64?  [1] batch int64?
__device__ float  g_w1s[3], g_w1d[3];
__device__ float  g_w2s[128], g_w2d[128];
__device__ float  g_w3s[64], g_w3d[64];

__device__ __forceinline__ float lrelu_exp(float e) {
    e = e > 0.f ? e : 0.2f * e;
    return __expf(e);
}

// ---------------- the single kernel, phase-dispatched ----------------
// P0 init+detect+proj (197)   P1 hist (3125)     P2 scan1 (196)
// P3 scan2 (1)                P4 scan3+dots1+pack (196)
// P5 scatter (3125)           P6 aggL1+dots2 (6250)
// P7 aggL2+pool+dots3 (6250)  P8 aggL3+dots4 (6250)
// P9 aggL4->recon + classifier (6258)
__global__ void __launch_bounds__(256) gat_kernel(KParams p) {
    __shared__ float sf[1088];
    int* si = (int*)sf;
    const int t = threadIdx.x;
    const int b = blockIdx.x;
    const int ph = p.phase;

    if (ph == 0) {                       // ---- init + detect + proj ----
        if (b < 196) {
            int i = b * 256 + t;
            if (i < NN) g_deg[i] = 0;
            if (i < BB * 64) g_pool[i] = 0.f;
            if (i < BB) g_cnt[i] = 0;
            if (b == 0 && t < 64) {
                int lane = t & 31;
                int nz = 0;
                if (t < 32) {
                    for (int k = lane; k < 128; k += 32) nz |= p.ei[2 * k + 1];
                } else {
                    for (int k = lane; k < 128; k += 32) nz |= p.batch[NN - 256 + 2 * k + 1];
                }
                #pragma unroll
                for (int o = 16; o; o >>= 1) nz |= __shfl_xor_sync(0xffffffffu, nz, o);
                if (lane == 0) g_flags[t < 32 ? 0 : 1] = (nz == 0) ? 1 : 0;
            }
        } else {                         // block 196: projections
            if (t < 128) {
                float s = 0.f, d = 0.f;
                for (int k = 0; k < 64; k++) {
                    float w = p.W2[t * 64 + k];
                    s = fmaf(w, p.a2s[k], s);
                    d = fmaf(w, p.a2d[k], d);
                }
                g_w2s[t] = s; g_w2d[t] = d;
            } else if (t < 192) {
                int i = t - 128;
                float s = 0.f, d = 0.f;
                for (int k = 0; k < 128; k++) {
                    float w = p.W3[i * 128 + k];
                    s = fmaf(w, p.a3s[k], s);
                    d = fmaf(w, p.a3d[k], d);
                }
                g_w3s[i] = s; g_w3d[i] = d;
            } else if (t < 195) {
                int i = t - 192;
                float s = 0.f;
                for (int k = 0; k < 128; k++) s = fmaf(p.W1[i * 128 + k], p.a1s[k], s);
                g_w1s[i] = s;
            } else if (t < 198) {
                int i = t - 195;
                float d = 0.f;
                for (int k = 0; k < 128; k++) d = fmaf(p.W1[i * 128 + k], p.a1d[k], d);
                g_w1d[i] = d;
            }
        }
    } else if (ph == 1) {                // ---- degree histogram ----
        int e = b * 256 + t;
        if (e < EE) {
            int r = g_flags[0] ? (int)((const long long*)p.ei)[(size_t)EE + e]
                               : p.ei[EE + e];
            atomicAdd(&g_deg[r], 1);
        }
    } else if (ph == 2) {                // ---- scan part 1 ----
        int i = b * 256 + t;
        int v = (i < NN) ? g_deg[i] : 0;
        si[t] = v;
        __syncthreads();
        #pragma unroll
        for (int d = 1; d < 256; d <<= 1) {
            int tv = (t >= d) ? si[t - d] : 0;
            __syncthreads();
            si[t] += tv;
            __syncthreads();
        }
        if (i < NN) g_off[i] = si[t] - v;
        if (t == 255) g_bsum[b] = si[255];
    } else if (ph == 3) {                // ---- scan part 2 ----
        int v = (t < 196) ? g_bsum[t] : 0;
        si[t] = v;
        __syncthreads();
        #pragma unroll
        for (int d = 1; d < 256; d <<= 1) {
            int tv = (t >= d) ? si[t - d] : 0;
            __syncthreads();
            si[t] += tv;
            __syncthreads();
        }
        if (t < 196) g_bsum[t] = si[t] - v;
    } else if (ph == 4) {                // ---- scan3 + dots1 + pack x ----
        int i = b * 256 + t;
        if (i < NN) {
            g_off[i] += g_bsum[b];
            g_deg[i] = 0;
            float x0 = p.x[i * 3 + 0], x1 = p.x[i * 3 + 1], x2 = p.x[i * 3 + 2];
            float hs = x0 * g_w1s[0] + x1 * g_w1s[1] + x2 * g_w1s[2];
            g_pkA[i] = make_float4(x0, x1, x2, hs);
            g_hdA[i] = x0 * g_w1d[0] + x1 * g_w1d[1] + x2 * g_w1d[2];
        }
        if (i == 0) g_off[NN] = EE;
    } else if (ph == 5) {                // ---- scatter to CSR ----
        int e = b * 256 + t;
        if (e < EE) {
            int r, s;
            if (g_flags[0]) {
                r = (int)((const long long*)p.ei)[(size_t)EE + e];
                s = (int)((const long long*)p.ei)[e];
            } else {
                r = p.ei[EE + e];
                s = p.ei[e];
            }
            int pos = g_off[r] + atomicAdd(&g_deg[r], 1);
            g_csr[pos] = (unsigned short)s;
        }
    } else if (ph == 6) {                // ---- aggL1 -> c, + inline dots2, pack ----
        int gw = (b * 256 + t) >> 5;
        int lane = t & 31;
        if (gw < NN) {
            int beg = g_off[gw], end = g_off[gw + 1];
            float hdi = g_hdA[gw];
            float s = 0.f, a0 = 0.f, a1 = 0.f, a2 = 0.f;
            for (int j = beg + lane; j < end; j += 32) {
                int sn = g_csr[j];
                float4 pk = g_pkA[sn];               // one 16B gather: x + hs
                float w = lrelu_exp(pk.w + hdi);
                s += w;
                a0 = fmaf(w, pk.x, a0);
                a1 = fmaf(w, pk.y, a1);
                a2 = fmaf(w, pk.z, a2);
            }
            #pragma unroll
            for (int o = 16; o; o >>= 1) {
                s  += __shfl_xor_sync(0xffffffffu, s, o);
                a0 += __shfl_xor_sync(0xffffffffu, a0, o);
                a1 += __shfl_xor_sync(0xffffffffu, a1, o);
                a2 += __shfl_xor_sync(0xffffffffu, a2, o);
            }
            float4 pks = g_pkA[gw];                  // self loop
            float ws = lrelu_exp(pks.w + hdi);
            s += ws;
            a0 = fmaf(ws, pks.x, a0);
            a1 = fmaf(ws, pks.y, a1);
            a2 = fmaf(ws, pks.z, a2);
            float inv = 1.f / s;
            float c0 = a0 * inv, c1 = a1 * inv, c2 = a2 * inv;
            // inline dots2: z = relu(c@W1+b1), hs2 = z.w2s, hd2 = z.w2d
            int k0 = lane * 4;
            float4 w0 = *(const float4*)&p.W1[0 * 128 + k0];
            float4 w1 = *(const float4*)&p.W1[1 * 128 + k0];
            float4 w2 = *(const float4*)&p.W1[2 * 128 + k0];
            float4 bb = *(const float4*)&p.b1[k0];
            float z0 = fmaxf(fmaf(c0, w0.x, fmaf(c1, w1.x, fmaf(c2, w2.x, bb.x))), 0.f);
            float z1 = fmaxf(fmaf(c0, w0.y, fmaf(c1, w1.y, fmaf(c2, w2.y, bb.y))), 0.f);
            float z2 = fmaxf(fmaf(c0, w0.z, fmaf(c1, w1.z, fmaf(c2, w2.z, bb.z))), 0.f);
            float z3 = fmaxf(fmaf(c0, w0.w, fmaf(c1, w1.w, fmaf(c2, w2.w, bb.w))), 0.f);
            float4 vs = *(const float4*)&g_w2s[k0];
            float4 vd = *(const float4*)&g_w2d[k0];
            float ss = z0 * vs.x + z1 * vs.y + z2 * vs.z + z3 * vs.w;
            float dd = z0 * vd.x + z1 * vd.y + z2 * vd.z + z3 * vd.w;
            #pragma unroll
            for (int o = 16; o; o >>= 1) {
                ss += __shfl_xor_sync(0xffffffffu, ss, o);
                dd += __shfl_xor_sync(0xffffffffu, dd, o);
            }
            if (lane == 0) {
                g_pkB[gw] = make_float4(c0, c1, c2, ss);
                g_hdB[gw] = dd;
            }
        }
    } else if (ph == 7) {                // ---- fused L2 -> latent + pool + dots3 ----
        int gw = (b * 256 + t) >> 5;
        int wid = (t >> 5) & 7;
        int lane = t & 31;
        if (gw < NN) {
            float* zsh = &sf[wid * 128];
            int beg = g_off[gw], end = g_off[gw + 1];
            float hdi = g_hdB[gw];
            int k0 = lane * 4;
            float4 w0 = *(const float4*)&p.W1[0 * 128 + k0];
            float4 w1 = *(const float4*)&p.W1[1 * 128 + k0];
            float4 w2 = *(const float4*)&p.W1[2 * 128 + k0];
            float4 bb = *(const float4*)&p.b1[k0];
            float s = 0.f;
            float acx = 0.f, acy = 0.f, acz = 0.f, acw = 0.f;
            for (int base = beg; base < end; base += 32) {
                int n = end - base; n = n < 32 ? n : 32;
                int sn_l = g_csr[base + (lane < n ? lane : n - 1)];  // coalesced stage
                for (int jj = 0; jj < n; jj++) {
                    int sn = __shfl_sync(0xffffffffu, sn_l, jj);
                    float4 pk = g_pkB[sn];           // one 16B gather: c + hs2
                    float w = lrelu_exp(pk.w + hdi);
                    s += w;
                    float z0 = fmaxf(fmaf(pk.x, w0.x, fmaf(pk.y, w1.x, fmaf(pk.z, w2.x, bb.x))), 0.f);
                    float z1 = fmaxf(fmaf(pk.x, w0.y, fmaf(pk.y, w1.y, fmaf(pk.z, w2.y, bb.y))), 0.f);
                    float z2 = fmaxf(fmaf(pk.x, w0.z, fmaf(pk.y, w1.z, fmaf(pk.z, w2.z, bb.z))), 0.f);
                    float z3 = fmaxf(fmaf(pk.x, w0.w, fmaf(pk.y, w1.w, fmaf(pk.z, w2.w, bb.w))), 0.f);
                    acx = fmaf(w, z0, acx);
                    acy = fmaf(w, z1, acy);
                    acz = fmaf(w, z2, acz);
                    acw = fmaf(w, z3, acw);
                }
            }
            {   // self loop
                float4 pk = g_pkB[gw];
                float w = lrelu_exp(pk.w + hdi);
                s += w;
                float z0 = fmaxf(fmaf(pk.x, w0.x, fmaf(pk.y, w1.x, fmaf(pk.z, w2.x, bb.x))), 0.f);
                float z1 = fmaxf(fmaf(pk.x, w0.y, fmaf(pk.y, w1.y, fmaf(pk.z, w2.y, bb.y))), 0.f);
                float z2 = fmaxf(fmaf(pk.x, w0.z, fmaf(pk.y, w1.z, fmaf(pk.z, w2.z, bb.z))), 0.f);
                float z3 = fmaxf(fmaf(pk.x, w0.w, fmaf(pk.y, w1.w, fmaf(pk.z, w2.w, bb.w))), 0.f);
                acx = fmaf(w, z0, acx);
                acy = fmaf(w, z1, acy);
                acz = fmaf(w, z2, acz);
                acw = fmaf(w, z3, acw);
            }
            float inv = 1.f / s;                     // uniform across lanes
            zsh[k0 + 0] = acx * inv;
            zsh[k0 + 1] = acy * inv;
            zsh[k0 + 2] = acz * inv;
            zsh[k0 + 3] = acw * inv;
            __syncwarp();
            int m = lane * 2;
            float o0 = p.b2[m], o1 = p.b2[m + 1];
            #pragma unroll 8
            for (int k = 0; k < 128; k++) {
                float zk = zsh[k];
                float2 w = *(const float2*)&p.W2[k * 64 + m];
                o0 = fmaf(zk, w.x, o0);
                o1 = fmaf(zk, w.y, o1);
            }
            p.latent[(size_t)gw * 64 + m]     = o0;
            p.latent[(size_t)gw * 64 + m + 1] = o1;
            // pooling (latent is in registers)
            int bi = g_flags[1] ? (int)((const long long*)p.batch)[gw] : p.batch[gw];
            atomicAdd(&g_pool[bi * 64 + m], o0);
            atomicAdd(&g_pool[bi * 64 + m + 1], o1);
            if (lane == 0) atomicAdd(&g_cnt[bi], 1);
            // inline dots3
            float ss = o0 * g_w3s[m] + o1 * g_w3s[m + 1];
            float dd = o0 * g_w3d[m] + o1 * g_w3d[m + 1];
            #pragma unroll
            for (int o = 16; o; o >>= 1) {
                ss += __shfl_xor_sync(0xffffffffu, ss, o);
                dd += __shfl_xor_sync(0xffffffffu, dd, o);
            }
            if (lane == 0) { g_hsA[gw] = ss; g_hdA[gw] = dd; }
        }
    } else if (ph == 8) {                // ---- fused L3 -> h4 + dots4, pack ----
        int gw = (b * 256 + t) >> 5;
        int wid = (t >> 5) & 7;
        int lane = t & 31;
        if (gw < NN) {
            float* dsh = &sf[wid * 64];
            int beg = g_off[gw], end = g_off[gw + 1];
            float hdi = g_hdA[gw];
            int m = lane * 2;
            float s = 0.f, ax = 0.f, ay = 0.f;
            for (int base = beg; base < end; base += 32) {
                int n = end - base; n = n < 32 ? n : 32;
                int idx = base + (lane < n ? lane : n - 1);
                int sn_l = g_csr[idx];               // coalesced stage
                float hs_l = g_hsA[sn_l];            // one gather per chunk per lane
                for (int jj = 0; jj < n; jj++) {
                    int sn = __shfl_sync(0xffffffffu, sn_l, jj);
                    float hsv = __shfl_sync(0xffffffffu, hs_l, jj);
                    float w = lrelu_exp(hsv + hdi);
                    float2 v = *(const float2*)&p.latent[(size_t)sn * 64 + m];
                    s += w;
                    ax = fmaf(w, v.x, ax);
                    ay = fmaf(w, v.y, ay);
                }
            }
            {   // self loop
                float w = lrelu_exp(g_hsA[gw] + hdi);
                float2 v = *(const float2*)&p.latent[(size_t)gw * 64 + m];
                s += w;
                ax = fmaf(w, v.x, ax);
                ay = fmaf(w, v.y, ay);
            }
            float inv = 1.f / s;
            dsh[m] = ax * inv;
            dsh[m + 1] = ay * inv;
            __syncwarp();
            int k0 = lane * 4;
            float4 acc = *(const float4*)&p.b3[k0];
            for (int i = 0; i < 64; i++) {
                float di = dsh[i];
                float4 w = *(const float4*)&p.W3[i * 128 + k0];
                acc.x = fmaf(di, w.x, acc.x);
                acc.y = fmaf(di, w.y, acc.y);
                acc.z = fmaf(di, w.z, acc.z);
                acc.w = fmaf(di, w.w, acc.w);
            }
            acc.x = fmaxf(acc.x, 0.f); acc.y = fmaxf(acc.y, 0.f);
            acc.z = fmaxf(acc.z, 0.f); acc.w = fmaxf(acc.w, 0.f);
            float a0 = acc.x * p.W4[(k0 + 0) * 3 + 0] + acc.y * p.W4[(k0 + 1) * 3 + 0]
                     + acc.z * p.W4[(k0 + 2) * 3 + 0] + acc.w * p.W4[(k0 + 3) * 3 + 0];
            float a1 = acc.x * p.W4[(k0 + 0) * 3 + 1] + acc.y * p.W4[(k0 + 1) * 3 + 1]
                     + acc.z * p.W4[(k0 + 2) * 3 + 1] + acc.w * p.W4[(k0 + 3) * 3 + 1];
            float a2 = acc.x * p.W4[(k0 + 0) * 3 + 2] + acc.y * p.W4[(k0 + 1) * 3 + 2]
                     + acc.z * p.W4[(k0 + 2) * 3 + 2] + acc.w * p.W4[(k0 + 3) * 3 + 2];
            #pragma unroll
            for (int o = 16; o; o >>= 1) {
                a0 += __shfl_xor_sync(0xffffffffu, a0, o);
                a1 += __shfl_xor_sync(0xffffffffu, a1, o);
                a2 += __shfl_xor_sync(0xffffffffu, a2, o);
            }
            if (lane == 0) {
                float hs4 = a0 * p.a4s[0] + a1 * p.a4s[1] + a2 * p.a4s[2];
                g_pkA[gw] = make_float4(a0, a1, a2, hs4);
                g_hdB[gw] = a0 * p.a4d[0] + a1 * p.a4d[1] + a2 * p.a4d[2];
            }
        }
    } else if (ph == 9) {                // ---- aggL4 -> recon, + classifier tail ----
        int lane = t & 31;
        if (b < 6250) {
            int gw = (b * 256 + t) >> 5;
            if (gw < NN) {
                int beg = g_off[gw], end = g_off[gw + 1];
                float hdi = g_hdB[gw];
                float s = 0.f, a0 = 0.f, a1 = 0.f, a2 = 0.f;
                for (int j = beg + lane; j < end; j += 32) {
                    int sn = g_csr[j];
                    float4 pk = g_pkA[sn];           // one 16B gather: h4 + hs4
                    float w = lrelu_exp(pk.w + hdi);
                    s += w;
                    a0 = fmaf(w, pk.x, a0);
                    a1 = fmaf(w, pk.y, a1);
                    a2 = fmaf(w, pk.z, a2);
                }
                #pragma unroll
                for (int o = 16; o; o >>= 1) {
                    s  += __shfl_xor_sync(0xffffffffu, s, o);
                    a0 += __shfl_xor_sync(0xffffffffu, a0, o);
                    a1 += __shfl_xor_sync(0xffffffffu, a1, o);
                    a2 += __shfl_xor_sync(0xffffffffu, a2, o);
                }
                float4 pks = g_pkA[gw];
                float ws = lrelu_exp(pks.w + hdi);
                s += ws;
                a0 = fmaf(ws, pks.x, a0);
                a1 = fmaf(ws, pks.y, a1);
                a2 = fmaf(ws, pks.z, a2);
                float inv = 1.f / s;
                if (lane == 0) {
                    p.recon[gw * 3 + 0] = a0 * inv + p.b4[0];
                    p.recon[gw * 3 + 1] = a1 * inv + p.b4[1];
                    p.recon[gw * 3 + 2] = a2 * inv + p.b4[2];
                }
            }
        } else {                         // classifier: blocks 6250..6257
            int wid = t >> 5;
            int g = (b - 6250) * 8 + wid;
            if (g < BB) {
                float* pp = &sf[wid * 64];
                float invc = 1.f / fmaxf((float)g_cnt[g], 1.f);
                pp[lane] = g_pool[g * 64 + lane] * invc;
                pp[lane + 32] = g_pool[g * 64 + lane + 32] * invc;
                __syncwarp();
                float z = p.bc1[lane];
                #pragma unroll 8
                for (int d = 0; d < 64; d++) z = fmaf(pp[d], p.Wc1[d * 32 + lane], z);
                z = fmaxf(z, 0.f);
                float o0 = z * p.Wc2[lane * 2 + 0];
                float o1 = z * p.Wc2[lane * 2 + 1];
                #pragma unroll
                for (int o = 16; o; o >>= 1) {
                    o0 += __shfl_xor_sync(0xffffffffu, o0, o);
                    o1 += __shfl_xor_sync(0xffffffffu, o1, o);
                }
                if (lane == 0) {
                    p.pred[g * 2 + 0] = o0 + p.bc2[0];
                    p.pred[g * 2 + 1] = o1 + p.bc2[1];
                }
            }
        }
    }
}

// ---------------- launcher ----------------
extern "C" void kernel_launch(void* const* d_in, const int* in_sizes, int n_in,
                              void* d_out, int out_size) {
    KParams p;
    p.x     = (const float*)d_in[0];
    p.ei    = (const int*)d_in[1];
    p.batch = (const int*)d_in[2];
    p.W1 = (const float*)d_in[3];  p.a1s = (const float*)d_in[4];
    p.a1d = (const float*)d_in[5]; p.b1  = (const float*)d_in[6];
    p.W2 = (const float*)d_in[7];  p.a2s = (const float*)d_in[8];
    p.a2d = (const float*)d_in[9]; p.b2  = (const float*)d_in[10];
    p.W3 = (const float*)d_in[11]; p.a3s = (const float*)d_in[12];
    p.a3d = (const float*)d_in[13];p.b3  = (const float*)d_in[14];
    p.W4 = (const float*)d_in[15]; p.a4s = (const float*)d_in[16];
    p.a4d = (const float*)d_in[17];p.b4  = (const float*)d_in[18];
    p.Wc1 = (const float*)d_in[19];p.bc1 = (const float*)d_in[20];
    p.Wc2 = (const float*)d_in[21];p.bc2 = (const float*)d_in[22];
    p.recon  = (float*)d_out;
    p.latent = (float*)d_out + 150000;
    p.pred   = (float*)d_out + 150000 + 3200000;

    const int nGrid = (NN + 255) / 256;          // 196
    const int eGrid = (EE + 255) / 256;          // 3125
    const int wGrid = (NN * 32 + 255) / 256;     // 6250

    p.phase = 0;  gat_kernel<<<nGrid + 1, 256>>>(p);  // init + detect + proj
    p.phase = 1;  gat_kernel<<<eGrid, 256>>>(p);      // histogram
    p.phase = 2;  gat_kernel<<<nGrid, 256>>>(p);      // scan (block)
    p.phase = 3;  gat_kernel<<<1, 256>>>(p);          // scan (sums)
    p.phase = 4;  gat_kernel<<<nGrid, 256>>>(p);      // scan (add) + dots1 + pack
    p.phase = 5;  gat_kernel<<<eGrid, 256>>>(p);      // scatter -> CSR
    p.phase = 6;  gat_kernel<<<wGrid, 256>>>(p);      // L1 agg + dots2
    p.phase = 7;  gat_kernel<<<wGrid, 256>>>(p);      // L2 fused + pool + dots3
    p.phase = 8;  gat_kernel<<<wGrid, 256>>>(p);      // L3 fused + dots4
    p.phase = 9;  gat_kernel<<<wGrid + 8, 256>>>(p);  // L4 agg -> recon + cls
}